// round 7
// baseline (speedup 1.0000x reference)
#include <cuda_runtime.h>

// EquivariantSubsample: 2x2 block-max pool with per-(b,c) offsets p_h, p_w in {0,1}.
// images: [B=16, C=64, H=512, W=512] fp32; out: [B, C, 256, 256] fp32.
// y_start(oy) = min(2*oy + p_h, H-2); x_start(ox) = min(2*ox + p_w, W-2).
//
// R5 base (189.2us best): 16 rows/CTA, 16384 CTAs, full unroll, shuffle-based
// neighbor fetch in pw==1 path, default stores (R6 showed __stcs is neutral).
// Single change this round: __ldcs (evict-first) on the bulk float4 input
// reads — the read stream has zero reuse, so don't let it occupy L2.

constexpr int H  = 512;
constexpr int W  = 512;
constexpr int OH = 256;
constexpr int OW = 256;
constexpr int ROWS_PER_BLOCK = 16;   // output rows per CTA
constexpr int THREADS = 256;         // 128 x-pair lanes * 2 row lanes

__global__ __launch_bounds__(THREADS)
void equivariant_subsample_kernel(const float* __restrict__ img,
                                  const int*   __restrict__ pw_arr,
                                  const int*   __restrict__ ph_arr,
                                  float* __restrict__ out)
{
    const int plane   = blockIdx.y;              // b*C + c  (0..1023)
    const int rowTile = blockIdx.x;              // 0..15

    const int ph = ph_arr[plane];
    const int pw = pw_arr[plane];

    const float* __restrict__ in = img + (size_t)plane * H * W;
    float* __restrict__ o        = out + (size_t)plane * OH * OW;

    const int j    = threadIdx.x & 127;          // x-pair index: covers ox = 2j, 2j+1
    const int ry   = threadIdx.x >> 7;           // 0 or 1: row lane within iteration
    const int lane = threadIdx.x & 31;

    if (pw == 0) {
        #pragma unroll
        for (int r = 0; r < ROWS_PER_BLOCK; r += 2) {
            const int oy = rowTile * ROWS_PER_BLOCK + r + ry;
            const int y0 = min(2 * oy + ph, H - 2);
            const float* __restrict__ r0 = in + (size_t)y0 * W;
            const float* __restrict__ r1 = r0 + W;

            // x pairs: (4j, 4j+1) and (4j+2, 4j+3) — one aligned float4 per row.
            const float4 a0 = __ldcs(reinterpret_cast<const float4*>(r0 + 4 * j));
            const float4 a1 = __ldcs(reinterpret_cast<const float4*>(r1 + 4 * j));
            float2 res;
            res.x = fmaxf(fmaxf(a0.x, a0.y), fmaxf(a1.x, a1.y));
            res.y = fmaxf(fmaxf(a0.z, a0.w), fmaxf(a1.z, a1.w));
            *reinterpret_cast<float2*>(o + (size_t)oy * OW + 2 * j) = res;
        }
    } else {
        #pragma unroll
        for (int r = 0; r < ROWS_PER_BLOCK; r += 2) {
            const int oy = rowTile * ROWS_PER_BLOCK + r + ry;
            const int y0 = min(2 * oy + ph, H - 2);
            const float* __restrict__ r0 = in + (size_t)y0 * W;
            const float* __restrict__ r1 = r0 + W;

            const float4 a0 = __ldcs(reinterpret_cast<const float4*>(r0 + 4 * j));
            const float4 a1 = __ldcs(reinterpret_cast<const float4*>(r1 + 4 * j));

            // Element 4j+4 lives in lane j+1's a0.x / a1.x.
            float n0 = __shfl_down_sync(0xffffffffu, a0.x, 1);
            float n1 = __shfl_down_sync(0xffffffffu, a1.x, 1);
            if (lane == 31 && j < 127) {           // warp boundary: j = 31, 63, 95
                n0 = r0[4 * j + 4];                // default hint: wants neighbor line cached
                n1 = r1[4 * j + 4];
            }

            float2 res;
            if (j < 127) {
                // x pairs: (4j+1, 4j+2) and (4j+3, 4j+4).
                res.x = fmaxf(fmaxf(a0.y, a0.z), fmaxf(a1.y, a1.z));
                res.y = fmaxf(fmaxf(a0.w, n0),   fmaxf(a1.w, n1));
            } else {
                // j==127: 4j = 508, a0 covers x=508..511.
                // ox=254 -> x=(509,510); ox=255 -> clamp: x_start=min(511,510)=510 -> (510,511).
                res.x = fmaxf(fmaxf(a0.y, a0.z), fmaxf(a1.y, a1.z));
                res.y = fmaxf(fmaxf(a0.z, a0.w), fmaxf(a1.z, a1.w));
            }
            *reinterpret_cast<float2*>(o + (size_t)oy * OW + 2 * j) = res;
        }
    }
}

extern "C" void kernel_launch(void* const* d_in, const int* in_sizes, int n_in,
                              void* d_out, int out_size)
{
    const float* img = (const float*)d_in[0];   // images fp32, B*C*H*W
    const int*   pw  = (const int*)d_in[1];     // p_w int32, B*C
    const int*   ph  = (const int*)d_in[2];     // p_h int32, B*C

    const int planes = in_sizes[1];             // B*C = 1024

    dim3 grid(OH / ROWS_PER_BLOCK, planes);     // (16, 1024)
    equivariant_subsample_kernel<<<grid, THREADS>>>(img, pw, ph, (float*)d_out);
}

// round 9
// speedup vs baseline: 1.1033x; 1.1033x over previous
#include <cuda_runtime.h>

// EquivariantSubsample: 2x2 block-max pool with per-(b,c) offsets p_h, p_w in {0,1}.
// images: [B=16, C=64, H=512, W=512] fp32; out: [B, C, 256, 256] fp32.
// y_start(oy) = min(2*oy + p_h, H-2); x_start(ox) = min(2*ox + p_w, W-2).
//
// FINAL (= R5, best measured 189.2us, DRAM 89.2%, HBM 7.07 TB/s = 88% of spec):
//   - 16 output rows per CTA, 16384 CTAs, fully unrolled row loop
//   - warp-uniform pw branch hoisted out of the loop
//   - pw==1 neighbor element fetched via __shfl_down (scalar LDG only on the
//     3 warp-boundary lanes) -> minimal L1 wavefronts
//   - DEFAULT cache operators: measured __stcs = neutral (R6), __ldcs = -5% (R7)
//   - occupancy deliberately not chased: measured anti-correlated with DRAM%.
// Remaining ~11% of DRAM-idle cycles are read/write turnaround + refresh;
// not recoverable by kernel changes (evidence: R4/R6/R7 lever sweeps).

constexpr int H  = 512;
constexpr int W  = 512;
constexpr int OH = 256;
constexpr int OW = 256;
constexpr int ROWS_PER_BLOCK = 16;   // output rows per CTA
constexpr int THREADS = 256;         // 128 x-pair lanes * 2 row lanes

__global__ __launch_bounds__(THREADS)
void equivariant_subsample_kernel(const float* __restrict__ img,
                                  const int*   __restrict__ pw_arr,
                                  const int*   __restrict__ ph_arr,
                                  float* __restrict__ out)
{
    const int plane   = blockIdx.y;              // b*C + c  (0..1023)
    const int rowTile = blockIdx.x;              // 0..15

    const int ph = ph_arr[plane];
    const int pw = pw_arr[plane];

    const float* __restrict__ in = img + (size_t)plane * H * W;
    float* __restrict__ o        = out + (size_t)plane * OH * OW;

    const int j    = threadIdx.x & 127;          // x-pair index: covers ox = 2j, 2j+1
    const int ry   = threadIdx.x >> 7;           // 0 or 1: row lane within iteration
    const int lane = threadIdx.x & 31;

    if (pw == 0) {
        #pragma unroll
        for (int r = 0; r < ROWS_PER_BLOCK; r += 2) {
            const int oy = rowTile * ROWS_PER_BLOCK + r + ry;
            const int y0 = min(2 * oy + ph, H - 2);
            const float* __restrict__ r0 = in + (size_t)y0 * W;
            const float* __restrict__ r1 = r0 + W;

            // x pairs: (4j, 4j+1) and (4j+2, 4j+3) — one aligned float4 per row.
            const float4 a0 = *reinterpret_cast<const float4*>(r0 + 4 * j);
            const float4 a1 = *reinterpret_cast<const float4*>(r1 + 4 * j);
            float2 res;
            res.x = fmaxf(fmaxf(a0.x, a0.y), fmaxf(a1.x, a1.y));
            res.y = fmaxf(fmaxf(a0.z, a0.w), fmaxf(a1.z, a1.w));
            *reinterpret_cast<float2*>(o + (size_t)oy * OW + 2 * j) = res;
        }
    } else {
        #pragma unroll
        for (int r = 0; r < ROWS_PER_BLOCK; r += 2) {
            const int oy = rowTile * ROWS_PER_BLOCK + r + ry;
            const int y0 = min(2 * oy + ph, H - 2);
            const float* __restrict__ r0 = in + (size_t)y0 * W;
            const float* __restrict__ r1 = r0 + W;

            const float4 a0 = *reinterpret_cast<const float4*>(r0 + 4 * j);
            const float4 a1 = *reinterpret_cast<const float4*>(r1 + 4 * j);

            // Element 4j+4 lives in lane j+1's a0.x / a1.x.
            float n0 = __shfl_down_sync(0xffffffffu, a0.x, 1);
            float n1 = __shfl_down_sync(0xffffffffu, a1.x, 1);
            if (lane == 31 && j < 127) {           // warp boundary: j = 31, 63, 95
                n0 = r0[4 * j + 4];
                n1 = r1[4 * j + 4];
            }

            float2 res;
            if (j < 127) {
                // x pairs: (4j+1, 4j+2) and (4j+3, 4j+4).
                res.x = fmaxf(fmaxf(a0.y, a0.z), fmaxf(a1.y, a1.z));
                res.y = fmaxf(fmaxf(a0.w, n0),   fmaxf(a1.w, n1));
            } else {
                // j==127: 4j = 508, a0 covers x=508..511.
                // ox=254 -> x=(509,510); ox=255 -> clamp: x_start=min(511,510)=510 -> (510,511).
                res.x = fmaxf(fmaxf(a0.y, a0.z), fmaxf(a1.y, a1.z));
                res.y = fmaxf(fmaxf(a0.z, a0.w), fmaxf(a1.z, a1.w));
            }
            *reinterpret_cast<float2*>(o + (size_t)oy * OW + 2 * j) = res;
        }
    }
}

extern "C" void kernel_launch(void* const* d_in, const int* in_sizes, int n_in,
                              void* d_out, int out_size)
{
    const float* img = (const float*)d_in[0];   // images fp32, B*C*H*W
    const int*   pw  = (const int*)d_in[1];     // p_w int32, B*C
    const int*   ph  = (const int*)d_in[2];     // p_h int32, B*C

    const int planes = in_sizes[1];             // B*C = 1024

    dim3 grid(OH / ROWS_PER_BLOCK, planes);     // (16, 1024)
    equivariant_subsample_kernel<<<grid, THREADS>>>(img, pw, ph, (float*)d_out);
}